// round 16
// baseline (speedup 1.0000x reference)
#include <cuda_runtime.h>
#include <math.h>

// ---------------- problem constants ----------------
#define NE     512        // num atoms
#define DIM    64         // embedding dim
#define NSIG   32768      // total signals (L*B = 1024*32)
#define SPAR   5          // sparsity level
#define NTHR   256        // threads per CTA (8 warps = 2 groups of 4)
#define SPW    4          // signals per warp
#define SPT    32         // signals per supertile (2 groups x 16)
#define NTILES 1024       // 32768 / 32
#define DSTR   516        // Ds smem row stride (padded)
#define GRID_MAIN 148

#define Z_ELEMS   2097152          // 32*64*32*32
#define LOSS_OFF  Z_ELEMS
#define COEF_OFF  (Z_ELEMS + 1)
#define COEF_ELEMS (NE * NSIG)     // 16777216

// smem offsets (bytes)
#define SMEM_DS_OFF   0                                   // Ds[64][516] f32
#define SMEM_XS_OFF   (DIM*DSTR*4)                        // 132096: XsT2[64][32] u64 (x dup)
#define SMEM_DD_OFF   (SMEM_XS_OFF + DIM*SPT*8)           // 148480: dd[512] f32
#define SMEM_SJ_OFF   (SMEM_DD_OFF + NE*4)                // 150528: SelJ[32][5] i32
#define SMEM_SA_OFF   (SMEM_SJ_OFF + SPT*SPAR*4)          // 151168: SelA[32][5] f32
#define SMEM_RD_OFF   (SMEM_SA_OFF + SPT*SPAR*4)          // 151808: redd[8] f64
#define SMEM_BYTES    (SMEM_RD_OFF + 8*8)                 // 151872

// group-scoped barrier: named barrier (1 or 2), 128 threads
#define GBAR(id) asm volatile("bar.sync %0, 128;" :: "r"(id) : "memory")

// ---------------- device globals (no cudaMalloc allowed) ----------------
__device__ float    g_Dn[DIM * NE];   // normalized dict, row-major [k][j]
__device__ float    g_dd[NE];         // ||d_j||^2 (post-normalize)
__device__ float    g_G[NE * NE];     // Gram, row-major [j][j']
__device__ double   g_sse;
__device__ unsigned g_done  = 0;      // finish ticket (omp)
__device__ unsigned g_ndone = 0;      // normalize-ready ticket (prep kernel)

// ---------------- packed helpers ----------------
__device__ __forceinline__ unsigned long long pk2(float a, float b) {
    unsigned long long r;
    asm("mov.b64 %0, {%1, %2};" : "=l"(r) : "f"(a), "f"(b));
    return r;
}
__device__ __forceinline__ void fma2(unsigned long long& c,
                                     unsigned long long a, unsigned long long b) {
    asm("fma.rn.f32x2 %0, %1, %2, %0;" : "+l"(c) : "l"(a), "l"(b));
}
__device__ __forceinline__ float f2lo(unsigned long long v) { return __uint_as_float((unsigned)v); }
__device__ __forceinline__ float f2hi(unsigned long long v) { return __uint_as_float((unsigned)(v >> 32)); }

// ---------------- fused prep + Gram + zero (R14's validated aux) ----------------
// CTA 0       : normalize dictionary (writes g_Dn/g_dd), reset g_sse, release ticket.
// CTAs 1-128  : spin on ticket, then 4 Gram rows each (sequential-k fmaf order).
// CTAs 129-511: zero the loss slot + coefficient region (~16us, BW floor).
__global__ void prep_gram_zero_kernel(const float* __restrict__ D, float* __restrict__ out) {
    const int tid = threadIdx.x;          // 256
    const int cta = blockIdx.x;           // 512

    if (cta == 0) {
        if (tid == 0) g_sse = 0.0;
        #pragma unroll
        for (int half = 0; half < 2; half++) {
            int j = tid + half * 256;
            float s = 0.f;
            #pragma unroll
            for (int k = 0; k < DIM; k++) { float v = D[k * NE + j]; s = fmaf(v, v, s); }
            float nm = fmaxf(sqrtf(s), 1e-10f);
            float s2 = 0.f;
            #pragma unroll
            for (int k = 0; k < DIM; k++) {
                float v = D[k * NE + j] / nm;   // division matches reference numerics
                g_Dn[k * NE + j] = v;
                s2 = fmaf(v, v, s2);
            }
            g_dd[j] = s2;
        }
        __syncthreads();
        if (tid == 0) { __threadfence(); atomicExch(&g_ndone, 1u); }   // release
        return;
    }

    if (cta <= 128) {
        __shared__ float scr[4 * DIM];
        if (tid == 0) {
            while (atomicAdd(&g_ndone, 0u) == 0u) __nanosleep(32);
            __threadfence();   // acquire
        }
        __syncthreads();

        const int jr = (cta - 1) * 4;
        for (int i = tid; i < 4 * DIM; i += NTHR) {
            int r = i & 3, k = i >> 2;
            scr[r * DIM + k] = g_Dn[k * NE + jr + r];
        }
        __syncthreads();
        #pragma unroll
        for (int half = 0; half < 2; half++) {
            int jp = tid + half * 256;
            float a0 = 0.f, a1 = 0.f, a2 = 0.f, a3 = 0.f;
            #pragma unroll 4
            for (int k = 0; k < DIM; k++) {
                float v = g_Dn[k * NE + jp];
                a0 = fmaf(scr[0 * DIM + k], v, a0);
                a1 = fmaf(scr[1 * DIM + k], v, a1);
                a2 = fmaf(scr[2 * DIM + k], v, a2);
                a3 = fmaf(scr[3 * DIM + k], v, a3);
            }
            g_G[(size_t)(jr + 0) * NE + jp] = a0;
            g_G[(size_t)(jr + 1) * NE + jp] = a1;
            g_G[(size_t)(jr + 2) * NE + jp] = a2;
            g_G[(size_t)(jr + 3) * NE + jp] = a3;
        }
        return;
    }

    {   // zero slice: CTAs 129-511 (383 CTAs)
        float4* p = (float4*)(out + Z_ELEMS);
        float4 z = make_float4(0.f, 0.f, 0.f, 0.f);
        const int n4 = COEF_ELEMS / 4;
        for (int i = (cta - 129) * NTHR + tid; i < n4; i += 383 * NTHR) p[i] = z;
        if (cta == 129 && tid == 0) out[Z_ELEMS + COEF_ELEMS] = 0.f;   // scalar tail
    }
}

// ---------------- main persistent OMP kernel: 2 phase-decoupled warp groups ----------------
__global__ void __launch_bounds__(NTHR, 1)
omp_kernel(const float* __restrict__ z_e, float* __restrict__ out) {
    extern __shared__ char smc[];
    float*              Ds   = (float*)(smc + SMEM_DS_OFF);              // [64][516]
    unsigned long long* XsT2 = (unsigned long long*)(smc + SMEM_XS_OFF); // [64][32] (x,x)
    float*              dd   = (float*)(smc + SMEM_DD_OFF);              // [512]
    int*                SelJ = (int*)(smc + SMEM_SJ_OFF);                // [32][5]
    float*              SelA = (float*)(smc + SMEM_SA_OFF);              // [32][5]
    double*             redd = (double*)(smc + SMEM_RD_OFF);             // [8]

    const int tid  = threadIdx.x;
    const int warp = tid >> 5, lane = tid & 31;
    const int g    = warp >> 2;               // group 0 (warps 0-3) / 1 (warps 4-7)
    const int wg   = warp & 3;                // warp within group (one per SMSP)
    const int gtid = tid & 127;               // thread id within group
    const int bid  = g + 1;                   // named barrier id (1 or 2)
    const int colb = g * 16 + wg * 4;         // this warp's 4 signal columns in XsT2
    const int sb   = g * 16 + wg * 4;         // this warp's signal base in Sel arrays
    const int jl4  = lane * 4;

    // ---- prefetch first supertile's x half for this group (16 signals) ----
    float xr[8];
    {
        const int t0 = blockIdx.x;
        const float* zb = z_e + (size_t)(t0 & 31) * (DIM * 1024) + (t0 >> 5) * SPT + g * 16;
        #pragma unroll
        for (int u = 0; u < 8; u++) {
            int i = u * 128 + gtid;                  // 1024 items / 128 threads
            xr[u] = zb[(i >> 4) * 1024 + (i & 15)];
        }
    }

    // ---- load dictionary + norms into smem ONCE (persistent; CTA-wide) ----
    for (int i4 = tid; i4 < (DIM * NE) / 4; i4 += NTHR) {
        int k = i4 >> 7, j4 = i4 & 127;
        ((float4*)(Ds + k * DSTR))[j4] = ((const float4*)g_Dn)[i4];
    }
    for (int i = tid; i < NE; i += NTHR) dd[i] = g_dd[i];
    __syncthreads();   // Ds/dd ready for both groups; groups decouple after this

    double sse_acc = 0.0;

    for (int tile = blockIdx.x; tile < NTILES; tile += gridDim.x) {
        const int batch = tile & 31;
        const int lbase = (tile >> 5) * SPT;

        GBAR(bid);    // this group's previous-tile epilogue readers done
        #pragma unroll
        for (int u = 0; u < 8; u++) {
            int i = u * 128 + gtid;
            XsT2[(i >> 4) * SPT + g * 16 + (i & 15)] = pk2(xr[u], xr[u]);
        }
        GBAR(bid);    // group's XsT2 half visible

        // ---- corr = Dn^T x, register-resident f32x2 pairs (identical to R14) ----
        unsigned long long c2[SPW][8];
        #pragma unroll
        for (int s = 0; s < SPW; s++)
            #pragma unroll
            for (int p = 0; p < 8; p++) c2[s][p] = 0ULL;

        {
            const float* dsl = Ds + jl4;
            #pragma unroll 8
            for (int k = 0; k < DIM; k++) {
                ulonglong2 xa = *(const ulonglong2*)&XsT2[k * SPT + colb];
                ulonglong2 xb = *(const ulonglong2*)&XsT2[k * SPT + colb + 2];
                #pragma unroll
                for (int tp = 0; tp < 4; tp++) {
                    ulonglong2 d = *(const ulonglong2*)&dsl[k * DSTR + 128 * tp];
                    fma2(c2[0][2*tp], d.x, xa.x); fma2(c2[0][2*tp+1], d.y, xa.x);
                    fma2(c2[1][2*tp], d.x, xa.y); fma2(c2[1][2*tp+1], d.y, xa.y);
                    fma2(c2[2][2*tp], d.x, xb.x); fma2(c2[2][2*tp+1], d.y, xb.x);
                    fma2(c2[3][2*tp], d.x, xb.y); fma2(c2[3][2*tp+1], d.y, xb.y);
                }
            }
        }

        // ---- 5 OMP selections (warp-local; identical comparator to R14) ----
        unsigned msk[SPW] = {0u, 0u, 0u, 0u};

        #pragma unroll
        for (int it = 0; it < SPAR; it++) {
            float bA[SPW], bV[SPW]; int bJ[SPW];

            #pragma unroll
            for (int s = 0; s < SPW; s++) {
                const unsigned m = msk[s];
                float ba = -1.f, bv = 0.f; int bj = 0;
                #pragma unroll
                for (int tp = 0; tp < 4; tp++) {
                    #pragma unroll
                    for (int pp = 0; pp < 2; pp++) {
                        unsigned long long v = c2[s][2*tp + pp];
                        const int j0   = 128*tp + jl4 + 2*pp;
                        const int slot = 4*tp + 2*pp;
                        if (!((m >> slot) & 1u)) {
                            float v0 = f2lo(v);
                            float a  = fabsf(v0);
                            if (a > ba) { ba = a; bv = v0; bj = j0; }
                        }
                        if (!((m >> (slot + 1)) & 1u)) {
                            float v1 = f2hi(v);
                            float a  = fabsf(v1);
                            if (a > ba) { ba = a; bv = v1; bj = j0 + 1; }
                        }
                    }
                }
                bA[s] = ba; bV[s] = bv; bJ[s] = bj;
            }
            #pragma unroll
            for (int s = 0; s < SPW; s++) {
                #pragma unroll
                for (int off = 16; off; off >>= 1) {
                    float oa = __shfl_xor_sync(0xffffffffu, bA[s], off);
                    float ov = __shfl_xor_sync(0xffffffffu, bV[s], off);
                    int   oj = __shfl_xor_sync(0xffffffffu, bJ[s], off);
                    if (oa > bA[s] || (oa == bA[s] && oj < bJ[s])) {
                        bA[s] = oa; bV[s] = ov; bJ[s] = oj;
                    }
                }
            }
            float alpha[SPW];
            #pragma unroll
            for (int s = 0; s < SPW; s++) {
                int j = bJ[s];
                alpha[s] = bV[s] / (dd[j] + 1e-10f);
                if (((j >> 2) & 31) == lane)
                    msk[s] |= 1u << (((j >> 7) << 2) | (j & 3));
            }
            if (lane == 0) {
                #pragma unroll
                for (int s = 0; s < SPW; s++) {
                    SelJ[(sb + s) * SPAR + it] = bJ[s];
                    SelA[(sb + s) * SPAR + it] = alpha[s];
                }
            }
            if (it < SPAR - 1) {
                #pragma unroll
                for (int s = 0; s < SPW; s++) {
                    const ulonglong2* gr =
                        (const ulonglong2*)(g_G + (size_t)bJ[s] * NE) + lane;
                    unsigned long long na = pk2(-alpha[s], -alpha[s]);
                    #pragma unroll
                    for (int tp = 0; tp < 4; tp++) {
                        ulonglong2 gg = __ldg(gr + 32 * tp);
                        fma2(c2[s][2*tp],     gg.x, na);
                        fma2(c2[s][2*tp + 1], gg.y, na);
                    }
                }
            }
        }

        // ---- prefetch next supertile's x half (LDG latency overlaps epilogue) ----
        {
            const int nt = tile + gridDim.x;
            if (nt < NTILES) {
                const float* zb = z_e + (size_t)(nt & 31) * (DIM * 1024)
                                      + (nt >> 5) * SPT + g * 16;
                #pragma unroll
                for (int u = 0; u < 8; u++) {
                    int i = u * 128 + gtid;
                    xr[u] = zb[(i >> 4) * 1024 + (i & 15)];
                }
            }
        }
        GBAR(bid);    // group's SelJ/SelA visible to its 4 warps

        // ---- epilogue (group-local 16 signals): recon, z store, sse, scatter ----
        {
            const int sigl = gtid & 15;            // 16 signals in this group
            const int kb   = (gtid >> 4) * 8;      // 8 dim-groups of 8
            int jj[SPAR]; float aa[SPAR];
            #pragma unroll
            for (int t = 0; t < SPAR; t++) {
                jj[t] = SelJ[(g * 16 + sigl) * SPAR + t];
                aa[t] = SelA[(g * 16 + sigl) * SPAR + t];
            }
            float* zo = out + (size_t)batch * (DIM * 1024) + lbase + g * 16;
            float ssl = 0.f;
            #pragma unroll
            for (int kk = 0; kk < 8; kk++) {
                int k = kb + kk;
                float acc = 0.f;
                #pragma unroll
                for (int t = 0; t < SPAR; t++)
                    acc = fmaf(Ds[k * DSTR + jj[t]], aa[t], acc);
                float x    = f2lo(XsT2[k * SPT + g * 16 + sigl]);
                float diff = acc - x;                 // z_dl - z_e
                ssl = fmaf(diff, diff, ssl);
                zo[k * 1024 + sigl] = x + diff;       // matches z_e + (z_dl - z_e)
            }
            sse_acc += (double)ssl;

            if (gtid < 16 * SPAR) {                   // 80 scatter stores per group
                int sg = gtid / SPAR, t = gtid - sg * SPAR;
                int sglob = (lbase + g * 16 + sg) * 32 + batch;
                out[COEF_OFF + (size_t)SelJ[(g * 16 + sg) * SPAR + t] * NSIG + sglob]
                    = SelA[(g * 16 + sg) * SPAR + t];
            }
        }
    }

    // ---- sse reduction + fused finish (grid ticket; CTA-wide rejoin) ----
    #pragma unroll
    for (int off = 16; off; off >>= 1)
        sse_acc += __shfl_xor_sync(0xffffffffu, sse_acc, off);
    if (lane == 0) redd[warp] = sse_acc;
    __syncthreads();
    if (tid == 0) {
        double tot = 0.0;
        #pragma unroll
        for (int w = 0; w < 8; w++) tot += redd[w];
        atomicAdd(&g_sse, tot);
        __threadfence();
        unsigned t = atomicAdd(&g_done, 1u);
        if (t == (unsigned)(gridDim.x - 1)) {
            g_done = 0;
            double s = atomicAdd(&g_sse, 0.0);
            out[LOSS_OFF] = (float)(1.25 * s / (double)Z_ELEMS);
        }
    }
}

// ---------------- launch ----------------
extern "C" void kernel_launch(void* const* d_in, const int* in_sizes, int n_in,
                              void* d_out, int out_size) {
    const float* z_e = (const float*)d_in[0];
    const float* D   = (const float*)d_in[1];
    if (n_in >= 2 && in_sizes[0] == DIM * NE && in_sizes[1] == Z_ELEMS) {
        const float* t = z_e; z_e = D; D = t;   // defensive order swap
    }
    float* out = (float*)d_out;

    cudaFuncSetAttribute(omp_kernel, cudaFuncAttributeMaxDynamicSharedMemorySize, SMEM_BYTES);

    prep_gram_zero_kernel<<<512, NTHR>>>(D, out);
    omp_kernel<<<GRID_MAIN, NTHR, SMEM_BYTES>>>(z_e, out);
}